// round 1
// baseline (speedup 1.0000x reference)
#include <cuda_runtime.h>
#include <cstdint>

#define BATCH 65536
#define DIM   512
#define EPSF  1e-15f
#define MAXNF 0.996f   // 1 - 4e-3

// ---------------- scratch (static device globals: allowed) ----------------
__device__ float g_xfc[(size_t)BATCH * DIM];   // A matrix (tf32-rounded fp32)
__device__ float g_w  [(size_t)BATCH * DIM];   // w = sinh(v)
__device__ float g_zt [DIM * DIM];             // z, tf32-rounded
__device__ float g_zn [DIM];
__device__ float g_ch [DIM];
__device__ float g_sh [DIM];
__device__ float g_fc2[BATCH];
__device__ float g_xc2[BATCH];
__device__ float g_s2p [4 * BATCH];            // per n-strip partials (deterministic)
__device__ float g_dxwp[4 * BATCH];
__device__ float g_f1[BATCH];
__device__ float g_f2[BATCH];

__device__ __forceinline__ unsigned f2tf(float f) {
    unsigned u; asm("cvt.rna.tf32.f32 %0, %1;" : "=r"(u) : "f"(f)); return u;
}

__device__ __forceinline__ void mma_tf32(float (&d)[4], const unsigned (&a)[4], const unsigned (&b)[2]) {
    asm volatile("mma.sync.aligned.m16n8k8.row.col.f32.tf32.tf32.f32 "
                 "{%0,%1,%2,%3}, {%4,%5,%6,%7}, {%8,%9}, {%0,%1,%2,%3};\n"
                 : "+f"(d[0]), "+f"(d[1]), "+f"(d[2]), "+f"(d[3])
                 : "r"(a[0]), "r"(a[1]), "r"(a[2]), "r"(a[3]),
                   "r"(b[0]), "r"(b[1]));
}

// ---------------- kernel 1: per-row prep -----------------------------------
// bt = logmap(x_prev, x_cur); x_fc = expmap0(bt) = Kfc*(ca*xp + cb*xc)
// also: fc2 = ||x_fc||^2 (scalar), xc2 = ||x_cur||^2, xc_out = projx(x_cur)
__global__ void k_prep(const float* __restrict__ xc, const float* __restrict__ xp,
                       float* __restrict__ out_xc)
{
    int row  = blockIdx.x * 8 + threadIdx.y;
    int lane = threadIdx.x;
    const float4* cv = (const float4*)(xc + (size_t)row * DIM);
    const float4* pv = (const float4*)(xp + (size_t)row * DIM);
    float4 c[4], p[4];
    float sxc = 0.f, sxp = 0.f, sxpc = 0.f;
#pragma unroll
    for (int i = 0; i < 4; i++) {
        c[i] = cv[lane + 32 * i];
        p[i] = pv[lane + 32 * i];
        sxc  += c[i].x*c[i].x + c[i].y*c[i].y + c[i].z*c[i].z + c[i].w*c[i].w;
        sxp  += p[i].x*p[i].x + p[i].y*p[i].y + p[i].z*p[i].z + p[i].w*p[i].w;
        sxpc += c[i].x*p[i].x + c[i].y*p[i].y + c[i].z*p[i].z + c[i].w*p[i].w;
    }
#pragma unroll
    for (int o = 16; o; o >>= 1) {
        sxc  += __shfl_xor_sync(0xffffffffu, sxc,  o);
        sxp  += __shfl_xor_sync(0xffffffffu, sxp,  o);
        sxpc += __shfl_xor_sync(0xffffffffu, sxpc, o);
    }
    // mobius_add(-xp, xc): x=-xp (x2=sxp), y=xc (y2=sxc), xy=-sxpc
    float xy  = -sxpc;
    float den = fmaxf(1.f + 2.f*xy + sxp*sxc, EPSF);
    float ca  = -(1.f + 2.f*xy + sxc) / den;   // coef on xp
    float cb  =  (1.f - sxp) / den;            // coef on xc
    float sub2 = ca*ca*sxp + 2.f*ca*cb*sxpc + cb*cb*sxc;
    float sn   = sqrtf(fmaxf(sub2, EPSF));
    float at   = atanhf(fminf(sn, 1.f - 1e-7f));
    float Kbt  = fmaxf(1.f - sxp, EPSF) * at / sn;          // bt = Kbt*sub
    float un   = sqrtf(fmaxf(Kbt*Kbt*sub2, EPSF));          // ||bt|| (clipped)
    float Kfc  = tanhf(un) / un * Kbt;                      // x_fc = Kfc*sub
    float fc2  = Kfc*Kfc*sub2;
    float nc   = sqrtf(fmaxf(sxc, EPSF));
    float pc   = nc > MAXNF ? MAXNF / nc : 1.f;
    if (lane == 0) { g_fc2[row] = fc2; g_xc2[row] = sxc; }

    float4* fo = (float4*)(g_xfc + (size_t)row * DIM);
    float4* xo = (float4*)(out_xc + (size_t)row * DIM);
#pragma unroll
    for (int i = 0; i < 4; i++) {
        float4 f, xq;
        f.x = __uint_as_float(f2tf(Kfc * (ca * p[i].x + cb * c[i].x)));
        f.y = __uint_as_float(f2tf(Kfc * (ca * p[i].y + cb * c[i].y)));
        f.z = __uint_as_float(f2tf(Kfc * (ca * p[i].z + cb * c[i].z)));
        f.w = __uint_as_float(f2tf(Kfc * (ca * p[i].w + cb * c[i].w)));
        xq.x = pc * c[i].x; xq.y = pc * c[i].y; xq.z = pc * c[i].z; xq.w = pc * c[i].w;
        fo[lane + 32 * i] = f;
        xo[lane + 32 * i] = xq;
    }
}

// ---------------- z preprocessing ------------------------------------------
__global__ void k_znorm(const float* __restrict__ z, const float* __restrict__ bias)
{
    int n = threadIdx.x;
    float acc = 0.f;
#pragma unroll 8
    for (int k = 0; k < DIM; k++) { float v = z[k * DIM + n]; acc += v * v; }
    g_zn[n] = sqrtf(fmaxf(acc, EPSF));
    float tb = 2.f * bias[n];
    g_ch[n] = coshf(tb);
    g_sh[n] = sinhf(tb);
}

__global__ void k_zcvt(const float* __restrict__ z)
{
    int i = blockIdx.x * 256 + threadIdx.x;   // grid = 1024 blocks
    g_zt[i] = __uint_as_float(f2tf(z[i]));
}

// ---------------- GEMM + fused w epilogue -----------------------------------
// Block tile 128x128, BK=32, 8 warps (2m x 4n), warp tile 64x32,
// mma.sync m16n8k8 tf32. XOR-swizzled smem: col = idx ^ (k>>3), stride 132.
__global__ void __launch_bounds__(256) k_gemm(const float* __restrict__ xcur)
{
    __shared__ float As[32][132];
    __shared__ float Bs[32][132];
    __shared__ float red_s2[4][128];
    __shared__ float red_dx[4][128];

    const int n0 = blockIdx.x * 128;   // gridDim.x = 4 (n-strips)
    const int m0 = blockIdx.y * 128;   // gridDim.y = 512
    const int tid = threadIdx.x;
    const int wid = tid >> 5, lane = tid & 31;
    const int g = lane >> 2, t = lane & 3;
    const int wm = wid & 1, wn = wid >> 1;
    const int mb = wm * 64, nb = wn * 32;

    float acc[4][4][4];
#pragma unroll
    for (int mi = 0; mi < 4; mi++)
#pragma unroll
        for (int ni = 0; ni < 4; ni++)
#pragma unroll
            for (int ci = 0; ci < 4; ci++) acc[mi][ni][ci] = 0.f;

    const int kc = tid & 31;   // k within tile (A load)
    const int rb = tid >> 5;   // row base (A load)

    for (int kt = 0; kt < 16; kt++) {
        int k0 = kt * 32;
#pragma unroll
        for (int i = 0; i < 16; i++) {
            int r = rb + 8 * i;
            As[kc][r ^ (kc >> 3)] = g_xfc[(size_t)(m0 + r) * DIM + k0 + kc];
        }
#pragma unroll
        for (int j = 0; j < 16; j++) {
            int idx = tid + 256 * j;
            int kk = idx >> 7, n = idx & 127;
            Bs[kk][n ^ (kk >> 3)] = g_zt[(k0 + kk) * DIM + n0 + n];
        }
        __syncthreads();
#pragma unroll
        for (int k8 = 0; k8 < 4; k8++) {
            int kb = k8 * 8;
            unsigned a[4][4], b[4][2];
#pragma unroll
            for (int mi = 0; mi < 4; mi++) {
                int r = mb + 16 * mi + g;
                a[mi][0] = __float_as_uint(As[kb + t    ][ r      ^ k8]);
                a[mi][1] = __float_as_uint(As[kb + t    ][(r + 8) ^ k8]);
                a[mi][2] = __float_as_uint(As[kb + t + 4][ r      ^ k8]);
                a[mi][3] = __float_as_uint(As[kb + t + 4][(r + 8) ^ k8]);
            }
#pragma unroll
            for (int ni = 0; ni < 4; ni++) {
                int c = nb + 8 * ni + g;
                b[ni][0] = __float_as_uint(Bs[kb + t    ][c ^ k8]);
                b[ni][1] = __float_as_uint(Bs[kb + t + 4][c ^ k8]);
            }
#pragma unroll
            for (int mi = 0; mi < 4; mi++)
#pragma unroll
                for (int ni = 0; ni < 4; ni++)
                    mma_tf32(acc[mi][ni], a[mi], b[ni]);
        }
        __syncthreads();
    }

    // ---- fused epilogue: w = sinh(2*zn*asinh((2*(raw/zn)*ch - (1+fc2)*sh)/max(1-fc2,eps)))
    float ps2[4][2], pdx[4][2];
#pragma unroll
    for (int mi = 0; mi < 4; mi++) { ps2[mi][0]=ps2[mi][1]=0.f; pdx[mi][0]=pdx[mi][1]=0.f; }

#pragma unroll
    for (int mi = 0; mi < 4; mi++) {
        int r0 = m0 + mb + 16 * mi + g;
        float f0 = g_fc2[r0], f1v = g_fc2[r0 + 8];
        float pa0 = 1.f + f0,  pa1 = 1.f + f1v;
        float id0 = 1.f / fmaxf(1.f - f0,  EPSF);
        float id1 = 1.f / fmaxf(1.f - f1v, EPSF);
#pragma unroll
        for (int ni = 0; ni < 4; ni++) {
            int c = n0 + nb + 8 * ni + 2 * t;
            float zn0 = g_zn[c], zn1 = g_zn[c + 1];
            float iz0 = 1.f / zn0, iz1 = 1.f / zn1;
            float ch0 = g_ch[c], ch1 = g_ch[c + 1];
            float sh0 = g_sh[c], sh1 = g_sh[c + 1];
            float in00 = acc[mi][ni][0] * iz0, in01 = acc[mi][ni][1] * iz1;
            float in10 = acc[mi][ni][2] * iz0, in11 = acc[mi][ni][3] * iz1;
            float w00 = sinhf(2.f * zn0 * asinhf((2.f * in00 * ch0 - pa0 * sh0) * id0));
            float w01 = sinhf(2.f * zn1 * asinhf((2.f * in01 * ch1 - pa0 * sh1) * id0));
            float w10 = sinhf(2.f * zn0 * asinhf((2.f * in10 * ch0 - pa1 * sh0) * id1));
            float w11 = sinhf(2.f * zn1 * asinhf((2.f * in11 * ch1 - pa1 * sh1) * id1));
            *(float2*)&g_w[(size_t)r0 * DIM + c]       = make_float2(w00, w01);
            *(float2*)&g_w[(size_t)(r0 + 8) * DIM + c] = make_float2(w10, w11);
            float2 x0 = *(const float2*)&xcur[(size_t)r0 * DIM + c];
            float2 x1 = *(const float2*)&xcur[(size_t)(r0 + 8) * DIM + c];
            ps2[mi][0] += w00 * w00 + w01 * w01;
            ps2[mi][1] += w10 * w10 + w11 * w11;
            pdx[mi][0] += w00 * x0.x + w01 * x0.y;
            pdx[mi][1] += w10 * x1.x + w11 * x1.y;
        }
    }
    // quad reduction (lanes differing in bits 0,1 share rows)
#pragma unroll
    for (int mi = 0; mi < 4; mi++)
#pragma unroll
        for (int h = 0; h < 2; h++) {
            ps2[mi][h] += __shfl_xor_sync(0xffffffffu, ps2[mi][h], 1);
            ps2[mi][h] += __shfl_xor_sync(0xffffffffu, ps2[mi][h], 2);
            pdx[mi][h] += __shfl_xor_sync(0xffffffffu, pdx[mi][h], 1);
            pdx[mi][h] += __shfl_xor_sync(0xffffffffu, pdx[mi][h], 2);
        }
    if (t == 0) {
#pragma unroll
        for (int mi = 0; mi < 4; mi++)
#pragma unroll
            for (int h = 0; h < 2; h++) {
                int rl = mb + 16 * mi + 8 * h + g;
                red_s2[wn][rl] = ps2[mi][h];
                red_dx[wn][rl] = pdx[mi][h];
            }
    }
    __syncthreads();
    if (tid < 128) {
        float s2 = red_s2[0][tid] + red_s2[1][tid] + red_s2[2][tid] + red_s2[3][tid];
        float dx = red_dx[0][tid] + red_dx[1][tid] + red_dx[2][tid] + red_dx[3][tid];
        g_s2p [(size_t)blockIdx.x * BATCH + m0 + tid] = s2;
        g_dxwp[(size_t)blockIdx.x * BATCH + m0 + tid] = dx;
    }
}

// ---------------- per-row scalar chain --------------------------------------
__global__ void k_scalars(const float* __restrict__ alpha, const float* __restrict__ stepsz)
{
    int row = blockIdx.x * 256 + threadIdx.x;
    float xc2 = g_xc2[row];
    float s2  = g_s2p[row] + g_s2p[BATCH + row] + g_s2p[2 * BATCH + row] + g_s2p[3 * BATCH + row];
    float dxw = g_dxwp[row] + g_dxwp[BATCH + row] + g_dxwp[2 * BATCH + row] + g_dxwp[3 * BATCH + row];
    float step = 1.f / (1.f + expf(-stepsz[0]));
    float av   = 1.f / (1.f + expf(-alpha[0]));

    // logmap0(poincare_fc): vel = kv * w
    float q  = sqrtf(1.f + s2);
    float yn = sqrtf(fmaxf(s2 / ((1.f + q) * (1.f + q)), EPSF));
    float kv = atanhf(fminf(yn, 1.f - 1e-7f)) / (yn * (1.f + q));
    // expmap(x_cur, step*vel): y_e = ky * w
    float un   = sqrtf(fmaxf(step * step * kv * kv * s2, EPSF));
    float lamf = fmaxf(1.f - xc2, EPSF);
    float th   = tanhf(un / lamf);
    float ky   = th * step * kv / un;
    float y2   = ky * ky * s2;
    float xy   = ky * dxw;
    float den  = fmaxf(1.f + 2.f * xy + xc2 * y2, EPSF);
    float c1   = (1.f + 2.f * xy + y2) / den;      // x_upd = c1*xc + c2*w
    float c2   = (1.f - xc2) * ky / den;
    // projx(x_upd)
    float nu2 = c1 * c1 * xc2 + 2.f * c1 * c2 * dxw + c2 * c2 * s2;
    float nu  = sqrtf(fmaxf(nu2, EPSF));
    float pu  = nu > MAXNF ? MAXNF / nu : 1.f;
    float b1 = pu * c1, b2 = pu * c2, nuf = pu * nu;
    // projx(x_cur)
    float nc  = sqrtf(fmaxf(xc2, EPSF));
    float pc  = nc > MAXNF ? MAXNF / nc : 1.f;
    float ncf = pc * nc;
    // mobius_scalar_mul(a, xc_p) and ((1-a), xu_p)
    float t1 = tanhf(av * atanhf(fminf(ncf, 1.f - 1e-7f)));
    float q1 = t1 * pc / ncf;                      // m1 = q1*xc
    float t2 = tanhf((1.f - av) * atanhf(fminf(nuf, 1.f - 1e-7f)));
    float q2 = t2 / nuf;
    float r1 = q2 * b1, r2 = q2 * b2;              // m2 = r1*xc + r2*w
    // mobius_add(m1, m2)
    float X2 = t1 * t1, Y2 = t2 * t2;
    float XY = q1 * (r1 * xc2 + r2 * dxw);
    float dn = fmaxf(1.f + 2.f * XY + X2 * Y2, EPSF);
    float h1 = ((1.f + 2.f * XY + Y2) * q1 + (1.f - X2) * r1) / dn;
    float h2 = (1.f - X2) * r2 / dn;
    // projx(x_next)
    float nn = sqrtf(fmaxf(h1 * h1 * xc2 + 2.f * h1 * h2 * dxw + h2 * h2 * s2, EPSF));
    float pn = nn > MAXNF ? MAXNF / nn : 1.f;
    g_f1[row] = pn * h1;
    g_f2[row] = pn * h2;
}

// ---------------- final rank-1 write ----------------------------------------
__global__ void k_final(const float* __restrict__ xcur, float* __restrict__ out)
{
    size_t i4 = (size_t)blockIdx.x * 256 + threadIdx.x;   // float4 index
    int row = (int)(i4 >> 7);
    float f1 = g_f1[row], f2 = g_f2[row];
    float4 xc = ((const float4*)xcur)[i4];
    float4 w  = ((const float4*)g_w)[i4];
    float4 o;
    o.x = f1 * xc.x + f2 * w.x;
    o.y = f1 * xc.y + f2 * w.y;
    o.z = f1 * xc.z + f2 * w.z;
    o.w = f1 * xc.w + f2 * w.w;
    ((float4*)out)[i4] = o;
}

// ---------------- launch -----------------------------------------------------
extern "C" void kernel_launch(void* const* d_in, const int* in_sizes, int n_in,
                              void* d_out, int out_size)
{
    const float* xcur   = (const float*)d_in[0];
    const float* xprev  = (const float*)d_in[1];
    const float* z      = (const float*)d_in[2];
    const float* bias   = (const float*)d_in[3];
    const float* alpha  = (const float*)d_in[4];
    const float* stepsz = (const float*)d_in[5];
    float* out = (float*)d_out;

    k_prep<<<BATCH / 8, dim3(32, 8)>>>(xcur, xprev, out + (size_t)BATCH * DIM);
    k_znorm<<<1, DIM>>>(z, bias);
    k_zcvt<<<(DIM * DIM) / 256, 256>>>(z);
    dim3 gg(4, BATCH / 128);
    k_gemm<<<gg, 256>>>(xcur);
    k_scalars<<<BATCH / 256, 256>>>(alpha, stepsz);
    k_final<<<(BATCH * (DIM / 4)) / 256, 256>>>(xcur, out);
}

// round 7
// speedup vs baseline: 1.8294x; 1.8294x over previous
#include <cuda_runtime.h>
#include <cstdint>

#define BATCH 65536
#define DIM   512
#define EPSF  1e-15f
#define MAXNF 0.996f   // 1 - 4e-3

// ---------------- scratch ----------------
__device__ float g_xfc[(size_t)BATCH * DIM];   // A matrix (tf32-rounded fp32)
__device__ float g_w  [(size_t)BATCH * DIM];   // w = sinh(v)
__device__ float g_zt [DIM * DIM];             // z^T tf32: g_zt[n*512+k] = z[k*512+n]
__device__ float g_zn [DIM];
__device__ float g_ch [DIM];
__device__ float g_sh [DIM];
__device__ float g_fc2[BATCH];
__device__ float g_xc2[BATCH];
__device__ float g_s2p [4 * BATCH];
__device__ float g_dxwp[4 * BATCH];
__device__ float g_f1[BATCH];
__device__ float g_f2[BATCH];

__device__ __forceinline__ unsigned f2tf(float f) {
    unsigned u; asm("cvt.rna.tf32.f32 %0, %1;" : "=r"(u) : "f"(f)); return u;
}
__device__ __forceinline__ uint32_t smem_u32(const void* p) {
    uint32_t a; asm("{ .reg .u64 t; cvta.to.shared.u64 t, %1; cvt.u32.u64 %0, t; }" : "=r"(a) : "l"(p));
    return a;
}
__device__ __forceinline__ void cpa16(uint32_t dst, const float* src) {
    asm volatile("cp.async.cg.shared.global [%0], [%1], 16;" :: "r"(dst), "l"(src));
}
#define CP_COMMIT() asm volatile("cp.async.commit_group;" ::: "memory")
#define CP_WAIT1()  asm volatile("cp.async.wait_group 1;" ::: "memory")

#define SWZ128(o) ((o) ^ (((o) >> 3) & 0x70))

__device__ __forceinline__ void mma_tf32(float (&d)[4], const unsigned (&a)[4], const unsigned (&b)[2]) {
    asm volatile("mma.sync.aligned.m16n8k8.row.col.f32.tf32.tf32.f32 "
                 "{%0,%1,%2,%3}, {%4,%5,%6,%7}, {%8,%9}, {%0,%1,%2,%3};\n"
                 : "+f"(d[0]), "+f"(d[1]), "+f"(d[2]), "+f"(d[3])
                 : "r"(a[0]), "r"(a[1]), "r"(a[2]), "r"(a[3]),
                   "r"(b[0]), "r"(b[1]));
}

// ---------------- kernel 1: per-row prep -----------------------------------
__global__ void k_prep(const float* __restrict__ xc, const float* __restrict__ xp,
                       float* __restrict__ out_xc)
{
    int row  = blockIdx.x * 8 + threadIdx.y;
    int lane = threadIdx.x;
    const float4* cv = (const float4*)(xc + (size_t)row * DIM);
    const float4* pv = (const float4*)(xp + (size_t)row * DIM);
    float4 c[4], p[4];
    float sxc = 0.f, sxp = 0.f, sxpc = 0.f;
#pragma unroll
    for (int i = 0; i < 4; i++) {
        c[i] = cv[lane + 32 * i];
        p[i] = pv[lane + 32 * i];
        sxc  += c[i].x*c[i].x + c[i].y*c[i].y + c[i].z*c[i].z + c[i].w*c[i].w;
        sxp  += p[i].x*p[i].x + p[i].y*p[i].y + p[i].z*p[i].z + p[i].w*p[i].w;
        sxpc += c[i].x*p[i].x + c[i].y*p[i].y + c[i].z*p[i].z + c[i].w*p[i].w;
    }
#pragma unroll
    for (int o = 16; o; o >>= 1) {
        sxc  += __shfl_xor_sync(0xffffffffu, sxc,  o);
        sxp  += __shfl_xor_sync(0xffffffffu, sxp,  o);
        sxpc += __shfl_xor_sync(0xffffffffu, sxpc, o);
    }
    float xy  = -sxpc;
    float den = fmaxf(1.f + 2.f*xy + sxp*sxc, EPSF);
    float ca  = -(1.f + 2.f*xy + sxc) / den;
    float cb  =  (1.f - sxp) / den;
    float sub2 = ca*ca*sxp + 2.f*ca*cb*sxpc + cb*cb*sxc;
    float sn   = sqrtf(fmaxf(sub2, EPSF));
    float at   = atanhf(fminf(sn, 1.f - 1e-7f));
    float Kbt  = fmaxf(1.f - sxp, EPSF) * at / sn;
    float un   = sqrtf(fmaxf(Kbt*Kbt*sub2, EPSF));
    float Kfc  = tanhf(un) / un * Kbt;
    float fc2  = Kfc*Kfc*sub2;
    float nc   = sqrtf(fmaxf(sxc, EPSF));
    float pc   = nc > MAXNF ? MAXNF / nc : 1.f;
    if (lane == 0) { g_fc2[row] = fc2; g_xc2[row] = sxc; }

    float4* fo = (float4*)(g_xfc + (size_t)row * DIM);
    float4* xo = (float4*)(out_xc + (size_t)row * DIM);
#pragma unroll
    for (int i = 0; i < 4; i++) {
        float4 f, xq;
        f.x = __uint_as_float(f2tf(Kfc * (ca * p[i].x + cb * c[i].x)));
        f.y = __uint_as_float(f2tf(Kfc * (ca * p[i].y + cb * c[i].y)));
        f.z = __uint_as_float(f2tf(Kfc * (ca * p[i].z + cb * c[i].z)));
        f.w = __uint_as_float(f2tf(Kfc * (ca * p[i].w + cb * c[i].w)));
        xq.x = pc * c[i].x; xq.y = pc * c[i].y; xq.z = pc * c[i].z; xq.w = pc * c[i].w;
        fo[lane + 32 * i] = f;
        xo[lane + 32 * i] = xq;
    }
}

// ---------------- z preprocessing ------------------------------------------
__global__ void k_znorm(const float* __restrict__ z, const float* __restrict__ bias)
{
    int n = threadIdx.x;
    float acc = 0.f;
#pragma unroll 8
    for (int k = 0; k < DIM; k++) { float v = z[k * DIM + n]; acc += v * v; }
    g_zn[n] = sqrtf(fmaxf(acc, EPSF));
    float tb = 2.f * bias[n];
    g_ch[n] = coshf(tb);
    g_sh[n] = sinhf(tb);
}

// transpose z -> g_zt[n*512+k] = tf32(z[k*512+n])
__global__ void k_ztr(const float* __restrict__ z)
{
    __shared__ float t[32][33];
    int bx = blockIdx.x & 15, by = blockIdx.x >> 4;
    int tx = threadIdx.x, ty = threadIdx.y;
    int r0 = by * 32, c0 = bx * 32;
#pragma unroll
    for (int i = 0; i < 4; i++)
        t[ty + 8 * i][tx] = z[(size_t)(r0 + ty + 8 * i) * DIM + c0 + tx];
    __syncthreads();
#pragma unroll
    for (int i = 0; i < 4; i++) {
        int rr = ty + 8 * i;
        g_zt[(size_t)(c0 + rr) * DIM + r0 + tx] = __uint_as_float(f2tf(t[tx][rr]));
    }
}

// ---------------- pipelined GEMM + fused w epilogue --------------------------
// Block 128x128, BK=32, 3-stage cp.async. Tiles row-major SW128-swizzled:
// element (r,k) at word r*32 + (k ^ 4*(r&7)). 8 warps (2m x 4n), warp 64x32.
static constexpr int STAGE_WORDS = 8192;        // 32KB: A 4096 words + B 4096 words
static constexpr int SMEM_BYTES  = 3 * 32768;   // 96KB

__global__ void __launch_bounds__(256)
k_gemm(const float* __restrict__ xcur)
{
    extern __shared__ __align__(1024) float smem[];
    const uint32_t sb = smem_u32(smem);

    const int n0 = blockIdx.x * 128;   // gridDim.x = 4
    const int m0 = blockIdx.y * 128;   // gridDim.y = 512
    const int tid = threadIdx.x;
    const int wid = tid >> 5, lane = tid & 31;
    const int g = lane >> 2, t = lane & 3;
    const int wm = wid & 1, wn = wid >> 1;
    const int mb = wm * 64, nb = wn * 32;

    float acc[4][4][4];
#pragma unroll
    for (int mi = 0; mi < 4; mi++)
#pragma unroll
        for (int ni = 0; ni < 4; ni++)
#pragma unroll
            for (int ci = 0; ci < 4; ci++) acc[mi][ni][ci] = 0.f;

    const int lr  = tid >> 3;          // load row 0..31 step (4 iters of +32... r = idx>>3)
    const int seg = tid & 7;

    auto load_tile = [&](int kt, int s) {
        const uint32_t st = sb + s * 32768;
        const float* Ab = g_xfc + (size_t)m0 * DIM + kt * 32;
        const float* Bb = g_zt  + (size_t)n0 * DIM + kt * 32;
#pragma unroll
        for (int i = 0; i < 4; i++) {
            int r = lr + 32 * i;
            uint32_t off = SWZ128((uint32_t)(r * 128 + seg * 16));
            cpa16(st + off,         Ab + (size_t)r * DIM + seg * 4);
            cpa16(st + 16384 + off, Bb + (size_t)r * DIM + seg * 4);
        }
        CP_COMMIT();
    };

    load_tile(0, 0);
    load_tile(1, 1);

    for (int kt = 0; kt < 16; kt++) {
        CP_WAIT1();
        __syncthreads();
        if (kt + 2 < 16) load_tile(kt + 2, (kt + 2) % 3);

        const float* As_f = smem + (kt % 3) * STAGE_WORDS;
        const float* Bs_f = As_f + 4096;
#pragma unroll
        for (int k8 = 0; k8 < 4; k8++) {
            const int kb = k8 * 8;
            const int k0 = (kb + t)     ^ (4 * g);
            const int k1 = (kb + t + 4) ^ (4 * g);
            unsigned a[4][4], b[4][2];
#pragma unroll
            for (int mi = 0; mi < 4; mi++) {
                int r = mb + 16 * mi + g;
                a[mi][0] = __float_as_uint(As_f[ r      * 32 + k0]);
                a[mi][1] = __float_as_uint(As_f[(r + 8) * 32 + k0]);
                a[mi][2] = __float_as_uint(As_f[ r      * 32 + k1]);
                a[mi][3] = __float_as_uint(As_f[(r + 8) * 32 + k1]);
            }
#pragma unroll
            for (int ni = 0; ni < 4; ni++) {
                int c = nb + 8 * ni + g;
                b[ni][0] = __float_as_uint(Bs_f[c * 32 + k0]);
                b[ni][1] = __float_as_uint(Bs_f[c * 32 + k1]);
            }
#pragma unroll
            for (int mi = 0; mi < 4; mi++)
#pragma unroll
                for (int ni = 0; ni < 4; ni++)
                    mma_tf32(acc[mi][ni], a[mi], b[ni]);
        }
    }
    __syncthreads();   // pipeline done; smem reused for reductions below

    float* red_s2 = smem;            // [4][128]
    float* red_dx = smem + 512;      // [4][128]

    // ---- fused epilogue: w = sinh(2*zn*asinh((2*(raw/zn)*ch - (1+fc2)*sh)/max(1-fc2,eps)))
    float ps2[4][2], pdx[4][2];
#pragma unroll
    for (int mi = 0; mi < 4; mi++) { ps2[mi][0]=ps2[mi][1]=0.f; pdx[mi][0]=pdx[mi][1]=0.f; }

#pragma unroll
    for (int mi = 0; mi < 4; mi++) {
        int r0 = m0 + mb + 16 * mi + g;
        float f0 = g_fc2[r0], f1v = g_fc2[r0 + 8];
        float pa0 = 1.f + f0,  pa1 = 1.f + f1v;
        float id0 = 1.f / fmaxf(1.f - f0,  EPSF);
        float id1 = 1.f / fmaxf(1.f - f1v, EPSF);
#pragma unroll
        for (int ni = 0; ni < 4; ni++) {
            int c = n0 + nb + 8 * ni + 2 * t;
            float zn0 = g_zn[c], zn1 = g_zn[c + 1];
            float iz0 = 1.f / zn0, iz1 = 1.f / zn1;
            float ch0 = g_ch[c], ch1 = g_ch[c + 1];
            float sh0 = g_sh[c], sh1 = g_sh[c + 1];
            float in00 = acc[mi][ni][0] * iz0, in01 = acc[mi][ni][1] * iz1;
            float in10 = acc[mi][ni][2] * iz0, in11 = acc[mi][ni][3] * iz1;
            float w00 = sinhf(2.f * zn0 * asinhf((2.f * in00 * ch0 - pa0 * sh0) * id0));
            float w01 = sinhf(2.f * zn1 * asinhf((2.f * in01 * ch1 - pa0 * sh1) * id0));
            float w10 = sinhf(2.f * zn0 * asinhf((2.f * in10 * ch0 - pa1 * sh0) * id1));
            float w11 = sinhf(2.f * zn1 * asinhf((2.f * in11 * ch1 - pa1 * sh1) * id1));
            *(float2*)&g_w[(size_t)r0 * DIM + c]       = make_float2(w00, w01);
            *(float2*)&g_w[(size_t)(r0 + 8) * DIM + c] = make_float2(w10, w11);
            float2 x0 = *(const float2*)&xcur[(size_t)r0 * DIM + c];
            float2 x1 = *(const float2*)&xcur[(size_t)(r0 + 8) * DIM + c];
            ps2[mi][0] += w00 * w00 + w01 * w01;
            ps2[mi][1] += w10 * w10 + w11 * w11;
            pdx[mi][0] += w00 * x0.x + w01 * x0.y;
            pdx[mi][1] += w10 * x1.x + w11 * x1.y;
        }
    }
#pragma unroll
    for (int mi = 0; mi < 4; mi++)
#pragma unroll
        for (int h = 0; h < 2; h++) {
            ps2[mi][h] += __shfl_xor_sync(0xffffffffu, ps2[mi][h], 1);
            ps2[mi][h] += __shfl_xor_sync(0xffffffffu, ps2[mi][h], 2);
            pdx[mi][h] += __shfl_xor_sync(0xffffffffu, pdx[mi][h], 1);
            pdx[mi][h] += __shfl_xor_sync(0xffffffffu, pdx[mi][h], 2);
        }
    if (t == 0) {
#pragma unroll
        for (int mi = 0; mi < 4; mi++)
#pragma unroll
            for (int h = 0; h < 2; h++) {
                int rl = mb + 16 * mi + 8 * h + g;
                red_s2[wn * 128 + rl] = ps2[mi][h];
                red_dx[wn * 128 + rl] = pdx[mi][h];
            }
    }
    __syncthreads();
    if (tid < 128) {
        float s2 = red_s2[tid] + red_s2[128 + tid] + red_s2[256 + tid] + red_s2[384 + tid];
        float dx = red_dx[tid] + red_dx[128 + tid] + red_dx[256 + tid] + red_dx[384 + tid];
        g_s2p [(size_t)blockIdx.x * BATCH + m0 + tid] = s2;
        g_dxwp[(size_t)blockIdx.x * BATCH + m0 + tid] = dx;
    }
}

// ---------------- per-row scalar chain --------------------------------------
__global__ void k_scalars(const float* __restrict__ alpha, const float* __restrict__ stepsz)
{
    int row = blockIdx.x * 256 + threadIdx.x;
    float xc2 = g_xc2[row];
    float s2  = g_s2p[row] + g_s2p[BATCH + row] + g_s2p[2 * BATCH + row] + g_s2p[3 * BATCH + row];
    float dxw = g_dxwp[row] + g_dxwp[BATCH + row] + g_dxwp[2 * BATCH + row] + g_dxwp[3 * BATCH + row];
    float step = 1.f / (1.f + expf(-stepsz[0]));
    float av   = 1.f / (1.f + expf(-alpha[0]));

    float q  = sqrtf(1.f + s2);
    float yn = sqrtf(fmaxf(s2 / ((1.f + q) * (1.f + q)), EPSF));
    float kv = atanhf(fminf(yn, 1.f - 1e-7f)) / (yn * (1.f + q));
    float un   = sqrtf(fmaxf(step * step * kv * kv * s2, EPSF));
    float lamf = fmaxf(1.f - xc2, EPSF);
    float th   = tanhf(un / lamf);
    float ky   = th * step * kv / un;
    float y2   = ky * ky * s2;
    float xy   = ky * dxw;
    float den  = fmaxf(1.f + 2.f * xy + xc2 * y2, EPSF);
    float c1   = (1.f + 2.f * xy + y2) / den;
    float c2   = (1.f - xc2) * ky / den;
    float nu2 = c1 * c1 * xc2 + 2.f * c1 * c2 * dxw + c2 * c2 * s2;
    float nu  = sqrtf(fmaxf(nu2, EPSF));
    float pu  = nu > MAXNF ? MAXNF / nu : 1.f;
    float b1 = pu * c1, b2 = pu * c2, nuf = pu * nu;
    float nc  = sqrtf(fmaxf(xc2, EPSF));
    float pc  = nc > MAXNF ? MAXNF / nc : 1.f;
    float ncf = pc * nc;
    float t1 = tanhf(av * atanhf(fminf(ncf, 1.f - 1e-7f)));
    float q1 = t1 * pc / ncf;
    float t2 = tanhf((1.f - av) * atanhf(fminf(nuf, 1.f - 1e-7f)));
    float q2 = t2 / nuf;
    float r1 = q2 * b1, r2 = q2 * b2;
    float X2 = t1 * t1, Y2 = t2 * t2;
    float XY = q1 * (r1 * xc2 + r2 * dxw);
    float dn = fmaxf(1.f + 2.f * XY + X2 * Y2, EPSF);
    float h1 = ((1.f + 2.f * XY + Y2) * q1 + (1.f - X2) * r1) / dn;
    float h2 = (1.f - X2) * r2 / dn;
    float nn = sqrtf(fmaxf(h1 * h1 * xc2 + 2.f * h1 * h2 * dxw + h2 * h2 * s2, EPSF));
    float pn = nn > MAXNF ? MAXNF / nn : 1.f;
    g_f1[row] = pn * h1;
    g_f2[row] = pn * h2;
}

// ---------------- final rank-1 write ----------------------------------------
__global__ void k_final(const float* __restrict__ xcur, float* __restrict__ out)
{
    size_t i4 = (size_t)blockIdx.x * 256 + threadIdx.x;
    int row = (int)(i4 >> 7);
    float f1 = g_f1[row], f2 = g_f2[row];
    float4 xc = ((const float4*)xcur)[i4];
    float4 w  = ((const float4*)g_w)[i4];
    float4 o;
    o.x = f1 * xc.x + f2 * w.x;
    o.y = f1 * xc.y + f2 * w.y;
    o.z = f1 * xc.z + f2 * w.z;
    o.w = f1 * xc.w + f2 * w.w;
    ((float4*)out)[i4] = o;
}

// ---------------- launch -----------------------------------------------------
extern "C" void kernel_launch(void* const* d_in, const int* in_sizes, int n_in,
                              void* d_out, int out_size)
{
    const float* xcur   = (const float*)d_in[0];
    const float* xprev  = (const float*)d_in[1];
    const float* z      = (const float*)d_in[2];
    const float* bias   = (const float*)d_in[3];
    const float* alpha  = (const float*)d_in[4];
    const float* stepsz = (const float*)d_in[5];
    float* out = (float*)d_out;

    cudaFuncSetAttribute(k_gemm, cudaFuncAttributeMaxDynamicSharedMemorySize, SMEM_BYTES);

    k_prep<<<BATCH / 8, dim3(32, 8)>>>(xcur, xprev, out + (size_t)BATCH * DIM);
    k_znorm<<<1, DIM>>>(z, bias);
    k_ztr<<<256, dim3(32, 8)>>>(z);
    dim3 gg(4, BATCH / 128);
    k_gemm<<<gg, 256, SMEM_BYTES>>>(xcur);
    k_scalars<<<BATCH / 256, 256>>>(alpha, stepsz);
    k_final<<<(BATCH * (DIM / 4)) / 256, 256>>>(xcur, out);
}